// round 13
// baseline (speedup 1.0000x reference)
#include <cuda_runtime.h>
#include <cuda_bf16.h>
#include <mma.h>
#include <cstdint>
#include <cstddef>

using namespace nvcuda;

// Problem constants
#define BB 2
#define LL 1024
#define HH 2048
#define HD 64
#define NQ 32
#define NK 4
#define NPREV 28

// Scratch (device globals)
__device__ float g_Q[(size_t)BB * NQ * LL * HD];
__device__ float g_K[(size_t)BB * NQ * LL * HD];
__device__ float g_V[(size_t)BB * NQ * LL * HD];
__device__ float g_AO[(size_t)BB * LL * (NQ * HD)];

// ---------------------------------------------------------------------------
// Double-buffered TF32 GEMM, BK=32, dynamic smem. C = A @ W^T.
// MODE 0: plain. MODE 1: Q scatter. MODE 2: fused KV scatter.
// ---------------------------------------------------------------------------
#define LDS 36   // 32 + 4 pad (floats); rows 144B, 16B-aligned

template<int BM, int BN, int WARPS_M, int WARPS_N, int MODE>
__global__ void __launch_bounds__(256, 2) gemm_pipe(
    const float* __restrict__ A, const float* __restrict__ W1,
    const float* __restrict__ W2, float* __restrict__ C1,
    float* __restrict__ C2, int M, int N, int K)
{
    constexpr int MI  = BM / (16 * WARPS_M);
    constexpr int NJ  = BN / (16 * WARPS_N);
    constexpr int APT = BM * 32 / (256 * 4);
    constexpr int BPT = BN * 32 / (256 * 4);
    constexpr int ABUF = BM * LDS;   // floats per A stage
    constexpr int BBUF = BN * LDS;

    extern __shared__ float gsm[];
    float* As = gsm;                  // [2][BM][LDS]
    float* Bs = gsm + 2 * ABUF;       // [2][BN][LDS]

    const int t    = threadIdx.x;
    const int warp = t >> 5;
    const int wm   = warp % WARPS_M;
    const int wn   = warp / WARPS_M;
    const int row0 = blockIdx.y * BM;
    const int col0 = blockIdx.x * BN;

    const float* aptr[APT];
    int ar[APT], ac[APT];
#pragma unroll
    for (int q = 0; q < APT; q++) {
        int f = q * 256 + t;
        ar[q] = f >> 3; ac[q] = (f & 7) * 4;
        aptr[q] = A + (size_t)(row0 + ar[q]) * K + ac[q];
    }
    const float* bptr[BPT];
    int br[BPT], bc[BPT];
#pragma unroll
    for (int q = 0; q < BPT; q++) {
        int f = q * 256 + t;
        br[q] = f >> 3; bc[q] = (f & 7) * 4;
        int rw = col0 + br[q];
        const float* src;
        if (MODE == 2) src = (rw < 256) ? (W1 + (size_t)rw * K)
                                        : (W2 + (size_t)(rw - 256) * K);
        else           src = W1 + (size_t)rw * K;
        bptr[q] = src + bc[q];
    }

    wmma::fragment<wmma::accumulator, 16, 16, 8, float> acc[MI][NJ];
#pragma unroll
    for (int i = 0; i < MI; i++)
#pragma unroll
        for (int j = 0; j < NJ; j++) wmma::fill_fragment(acc[i][j], 0.0f);

    float4 ra[APT], rb[BPT];

    auto ldg = [&](int bk) {
#pragma unroll
        for (int q = 0; q < APT; q++) ra[q] = *(const float4*)(aptr[q] + bk);
#pragma unroll
        for (int q = 0; q < BPT; q++) rb[q] = *(const float4*)(bptr[q] + bk);
    };
    auto sts = [&](int buf) {
#pragma unroll
        for (int q = 0; q < APT; q++) {
            float* d = As + buf * ABUF + ar[q] * LDS + ac[q];
            d[0] = wmma::__float_to_tf32(ra[q].x);
            d[1] = wmma::__float_to_tf32(ra[q].y);
            d[2] = wmma::__float_to_tf32(ra[q].z);
            d[3] = wmma::__float_to_tf32(ra[q].w);
        }
#pragma unroll
        for (int q = 0; q < BPT; q++) {
            float* d = Bs + buf * BBUF + br[q] * LDS + bc[q];
            d[0] = wmma::__float_to_tf32(rb[q].x);
            d[1] = wmma::__float_to_tf32(rb[q].y);
            d[2] = wmma::__float_to_tf32(rb[q].z);
            d[3] = wmma::__float_to_tf32(rb[q].w);
        }
    };
    auto compute = [&](int buf) {
#pragma unroll
        for (int ks = 0; ks < 4; ks++) {
            wmma::fragment<wmma::matrix_a, 16, 16, 8, wmma::precision::tf32,
                           wmma::row_major> af[MI];
#pragma unroll
            for (int i = 0; i < MI; i++)
                wmma::load_matrix_sync(af[i],
                    As + buf * ABUF + (wm * MI + i) * 16 * LDS + ks * 8, LDS);
#pragma unroll
            for (int j = 0; j < NJ; j++) {
                wmma::fragment<wmma::matrix_b, 16, 16, 8, wmma::precision::tf32,
                               wmma::col_major> bf;
                wmma::load_matrix_sync(bf,
                    Bs + buf * BBUF + (wn * NJ + j) * 16 * LDS + ks * 8, LDS);
#pragma unroll
                for (int i = 0; i < MI; i++)
                    wmma::mma_sync(acc[i][j], af[i], bf, acc[i][j]);
            }
        }
    };

    const int nit = K / 32;
    ldg(0);
    sts(0);
    __syncthreads();
    for (int i = 0; i < nit; i++) {
        int buf = i & 1;
        if (i + 1 < nit) ldg((i + 1) * 32);
        compute(buf);
        if (i + 1 < nit) {
            sts(buf ^ 1);
            __syncthreads();
        }
    }

#pragma unroll
    for (int i = 0; i < MI; i++) {
        int m0 = row0 + (wm * MI + i) * 16;
#pragma unroll
        for (int j = 0; j < NJ; j++) {
            int n0 = col0 + (wn * NJ + j) * 16;
            if (MODE == 0) {
                wmma::store_matrix_sync(C1 + (size_t)m0 * N + n0, acc[i][j], N,
                                        wmma::mem_row_major);
            } else if (MODE == 1) {
                int b = m0 >> 10, l = m0 & 1023;
                int h = n0 >> 6,  d = n0 & 63;
                float* dst = C1 + ((size_t)((b * 32 + h) * 1024 + l)) * 64 + d;
                wmma::store_matrix_sync(dst, acc[i][j], 64, wmma::mem_row_major);
            } else {
                int b = m0 >> 10, l = m0 & 1023;
                int h = n0 >> 6,  d = n0 & 63;
                float* dst;
                if (h < 4)
                    dst = C1 + ((size_t)((b * 32 + NPREV + h) * 1024 + l)) * 64 + d;
                else
                    dst = C2 + ((size_t)((b * 32 + NPREV + h - 4) * 1024 + l)) * 64 + d;
                wmma::store_matrix_sync(dst, acc[i][j], 64, wmma::mem_row_major);
            }
        }
    }
}

// ---------------------------------------------------------------------------
// RoPE + cache gather (unchanged)
// ---------------------------------------------------------------------------
__global__ void __launch_bounds__(256) rope_gather_kernel(
    const float* __restrict__ prev_k, const float* __restrict__ prev_v,
    const float* __restrict__ cosp,   const float* __restrict__ sinp)
{
    unsigned t = blockIdx.x * 256u + threadIdx.x;
    int d = t & 31;
    int l = (t >> 5) & 1023;
    int h = (t >> 15) & 31;
    int b = t >> 20;

    float c = cosp[l * 64 + d];
    float s = sinp[l * 64 + d];

    size_t base = ((size_t)(b * 32 + h) * 1024 + l) * 64;

    {
        float* q = g_Q + base;
        float x1 = q[d], x2 = q[d + 32];
        q[d]      = x1 * c - x2 * s;
        q[d + 32] = x2 * c + x1 * s;
    }
    {
        float* k = g_K + base;
        float y1, y2;
        if (h < NPREV) {
            const float* pk = prev_k + ((size_t)(b * NPREV + h) * 1024 + l) * 64;
            y1 = pk[d]; y2 = pk[d + 32];
        } else {
            y1 = k[d]; y2 = k[d + 32];
        }
        k[d]      = y1 * c - y2 * s;
        k[d + 32] = y2 * c + y1 * s;
    }
    if (h < NPREV) {
        const float* pv = prev_v + ((size_t)(b * NPREV + h) * 1024 + l) * 64;
        float* v = g_V + base;
        v[d]      = pv[d];
        v[d + 32] = pv[d + 32];
    }
}

// ---------------------------------------------------------------------------
// Flash attention, tf32 wmma, O resident in accumulator fragments.
// Rescale via accumulator-layout broadcast fragment (documented elementwise op).
// KV prefetched to registers ahead of the consuming sync.
// ---------------------------------------------------------------------------
#define FLD  68
#define CTLD 20
#define FSM  ((4 * 64 * FLD + 64 * CTLD) * 4)

__global__ void __launch_bounds__(256, 2) flash_wmma(
    const float* __restrict__ Q, const float* __restrict__ K,
    const float* __restrict__ V, float* __restrict__ AO)
{
    extern __shared__ float sm[];
    float* Qs = sm;                 // tf32
    float* Ks = sm + 64 * FLD;      // tf32
    float* Vs = sm + 2 * 64 * FLD;  // tf32
    float* Ss = sm + 3 * 64 * FLD;  // fp32 scores -> tf32 P; reused for O out
    float* Ct = sm + 4 * 64 * FLD;  // 64 x CTLD corr broadcast tile

    const int t    = threadIdx.x;
    const int warp = t >> 5;
    const int wm   = warp & 3;   // rows 16*wm..+15
    const int wn   = warp >> 2;  // d-cols 32*wn..+31
    const int qt   = blockIdx.x;
    const int h    = blockIdx.y;
    const int b    = blockIdx.z;
    const int q0   = qt * 64;

    const size_t bh_off = (size_t)(b * 32 + h) * 1024 * 64;
    const float* Qp = Q + bh_off;
    const float* Kp = K + bh_off;
    const float* Vp = V + bh_off;

    float4 rk[4], rv[4];
    int fr[4], fc[4];
#pragma unroll
    for (int q = 0; q < 4; q++) {
        int f = q * 256 + t;
        fr[q] = f >> 4; fc[q] = (f & 15) * 4;
    }

    auto kv_ldg = [&](int j) {
#pragma unroll
        for (int q = 0; q < 4; q++) {
            size_t goff = (size_t)(j * 64 + fr[q]) * 64 + fc[q];
            rk[q] = *(const float4*)(Kp + goff);
            rv[q] = *(const float4*)(Vp + goff);
        }
    };
    auto kv_sts = [&]() {
#pragma unroll
        for (int q = 0; q < 4; q++) {
            float* dk = Ks + fr[q] * FLD + fc[q];
            dk[0] = wmma::__float_to_tf32(rk[q].x);
            dk[1] = wmma::__float_to_tf32(rk[q].y);
            dk[2] = wmma::__float_to_tf32(rk[q].z);
            dk[3] = wmma::__float_to_tf32(rk[q].w);
            float* dv = Vs + fr[q] * FLD + fc[q];
            dv[0] = wmma::__float_to_tf32(rv[q].x);
            dv[1] = wmma::__float_to_tf32(rv[q].y);
            dv[2] = wmma::__float_to_tf32(rv[q].z);
            dv[3] = wmma::__float_to_tf32(rv[q].w);
        }
    };

    // Load Q tile (tf32) + first KV tile
#pragma unroll
    for (int q = 0; q < 4; q++) {
        float4 v = *(const float4*)(Qp + (size_t)(q0 + fr[q]) * 64 + fc[q]);
        float* dq = Qs + fr[q] * FLD + fc[q];
        dq[0] = wmma::__float_to_tf32(v.x);
        dq[1] = wmma::__float_to_tf32(v.y);
        dq[2] = wmma::__float_to_tf32(v.z);
        dq[3] = wmma::__float_to_tf32(v.w);
    }
    kv_ldg(0);
    kv_sts();
    __syncthreads();

    wmma::fragment<wmma::accumulator, 16, 16, 8, float> oacc[2];
#pragma unroll
    for (int n = 0; n < 2; n++) wmma::fill_fragment(oacc[n], 0.0f);

    const int srow = t >> 2;
    const int scol = (t & 3) * 16;
    float m_r = -1e30f, l_r = 0.0f;

    for (int j = 0; j <= qt; j++) {
        if (j < qt) kv_ldg(j + 1);   // prefetch next tile into registers

        // S = Q @ K^T
        {
            wmma::fragment<wmma::accumulator, 16, 16, 8, float> sacc[2];
#pragma unroll
            for (int n = 0; n < 2; n++) wmma::fill_fragment(sacc[n], 0.0f);
#pragma unroll
            for (int ks = 0; ks < 8; ks++) {
                wmma::fragment<wmma::matrix_a, 16, 16, 8, wmma::precision::tf32,
                               wmma::row_major> af;
                wmma::load_matrix_sync(af, Qs + (wm * 16) * FLD + ks * 8, FLD);
#pragma unroll
                for (int n = 0; n < 2; n++) {
                    wmma::fragment<wmma::matrix_b, 16, 16, 8, wmma::precision::tf32,
                                   wmma::col_major> bf;
                    wmma::load_matrix_sync(bf, Ks + (wn * 32 + n * 16) * FLD + ks * 8, FLD);
                    wmma::mma_sync(sacc[n], af, bf, sacc[n]);
                }
            }
#pragma unroll
            for (int n = 0; n < 2; n++)
                wmma::store_matrix_sync(Ss + (wm * 16) * FLD + wn * 32 + n * 16,
                                        sacc[n], FLD, wmma::mem_row_major);
        }
        __syncthreads();   // Ss visible; Ks consumers done

        // Online softmax (4 threads per row); write P (tf32) + corr tile
        {
            float sv[16];
#pragma unroll
            for (int i4 = 0; i4 < 4; i4++) {
                float4 v = *(const float4*)(Ss + srow * FLD + scol + i4 * 4);
                sv[i4 * 4 + 0] = v.x * 0.125f;
                sv[i4 * 4 + 1] = v.y * 0.125f;
                sv[i4 * 4 + 2] = v.z * 0.125f;
                sv[i4 * 4 + 3] = v.w * 0.125f;
            }
            if (j == qt) {
#pragma unroll
                for (int i = 0; i < 16; i++)
                    if (scol + i > srow) sv[i] = -1e30f;
            }
            float mx = sv[0];
#pragma unroll
            for (int i = 1; i < 16; i++) mx = fmaxf(mx, sv[i]);
            mx = fmaxf(mx, __shfl_xor_sync(0xffffffffu, mx, 1));
            mx = fmaxf(mx, __shfl_xor_sync(0xffffffffu, mx, 2));
            float mnew = fmaxf(m_r, mx);
            float corr = __expf(m_r - mnew);
            float rs = 0.0f;
#pragma unroll
            for (int i = 0; i < 16; i++) {
                sv[i] = __expf(sv[i] - mnew);
                rs += sv[i];
            }
            rs += __shfl_xor_sync(0xffffffffu, rs, 1);
            rs += __shfl_xor_sync(0xffffffffu, rs, 2);
            l_r = l_r * corr + rs;
            m_r = mnew;
#pragma unroll
            for (int i4 = 0; i4 < 4; i4++) {
                float4 p;
                p.x = wmma::__float_to_tf32(sv[i4 * 4 + 0]);
                p.y = wmma::__float_to_tf32(sv[i4 * 4 + 1]);
                p.z = wmma::__float_to_tf32(sv[i4 * 4 + 2]);
                p.w = wmma::__float_to_tf32(sv[i4 * 4 + 3]);
                *(float4*)(Ss + srow * FLD + scol + i4 * 4) = p;
            }
            // corr broadcast tile: this thread covers cols (t&3)*4..+3 of row srow
            float* cd = Ct + srow * CTLD + (t & 3) * 4;
            cd[0] = corr; cd[1] = corr; cd[2] = corr; cd[3] = corr;
        }
        __syncthreads();   // P + Ct visible

        // O *= corr (elementwise via accumulator-layout fragment), then O += P@V
        {
            wmma::fragment<wmma::accumulator, 16, 16, 8, float> cf;
            wmma::load_matrix_sync(cf, Ct + (wm * 16) * CTLD, CTLD,
                                   wmma::mem_row_major);
#pragma unroll
            for (int n = 0; n < 2; n++)
#pragma unroll
                for (int e = 0; e < cf.num_elements; e++)
                    oacc[n].x[e] *= cf.x[e];

#pragma unroll
            for (int ks = 0; ks < 8; ks++) {
                wmma::fragment<wmma::matrix_a, 16, 16, 8, wmma::precision::tf32,
                               wmma::row_major> af;
                wmma::load_matrix_sync(af, Ss + (wm * 16) * FLD + ks * 8, FLD);
#pragma unroll
                for (int n = 0; n < 2; n++) {
                    wmma::fragment<wmma::matrix_b, 16, 16, 8, wmma::precision::tf32,
                                   wmma::row_major> bf;
                    wmma::load_matrix_sync(bf, Vs + (ks * 8) * FLD + wn * 32 + n * 16, FLD);
                    wmma::mma_sync(oacc[n], af, bf, oacc[n]);
                }
            }
        }
        __syncthreads();   // Ss + Vs consumers done

        if (j < qt) {
            kv_sts();      // write prefetched tile j+1
            __syncthreads();
        }
    }

    // Epilogue: O frags -> Ss, normalize, write AO
#pragma unroll
    for (int n = 0; n < 2; n++)
        wmma::store_matrix_sync(Ss + (wm * 16) * FLD + wn * 32 + n * 16,
                                oacc[n], FLD, wmma::mem_row_major);
    __syncthreads();
    {
        float rl = 1.0f / l_r;
        size_t row = (size_t)b * 1024 + (q0 + srow);
        float* dst = AO + row * 2048 + h * 64 + scol;
#pragma unroll
        for (int i4 = 0; i4 < 4; i4++) {
            float4 o = *(const float4*)(Ss + srow * FLD + scol + i4 * 4);
            o.x *= rl; o.y *= rl; o.z *= rl; o.w *= rl;
            *(float4*)(dst + i4 * 4) = o;
        }
    }
}

// ---------------------------------------------------------------------------
// Launch
// ---------------------------------------------------------------------------
extern "C" void kernel_launch(void* const* d_in, const int* in_sizes, int n_in,
                              void* d_out, int out_size)
{
    const float* hs   = (const float*)d_in[0];
    const float* pk   = (const float*)d_in[1];
    const float* pv   = (const float*)d_in[2];
    const float* Wq   = (const float*)d_in[3];
    const float* Wk   = (const float*)d_in[4];
    const float* Wv   = (const float*)d_in[5];
    const float* Wo   = (const float*)d_in[6];
    const float* cosp = (const float*)d_in[7];
    const float* sinp = (const float*)d_in[8];
    float* out = (float*)d_out;

    float *Qb, *Kb, *Vb, *AO;
    cudaGetSymbolAddress((void**)&Qb, g_Q);
    cudaGetSymbolAddress((void**)&Kb, g_K);
    cudaGetSymbolAddress((void**)&Vb, g_V);
    cudaGetSymbolAddress((void**)&AO, g_AO);

    const int smem_g128 = 2 * (128 + 128) * LDS * 4;  // 73728
    const int smem_g64  = 2 * (64 + 128) * LDS * 4;   // 55296

    cudaFuncSetAttribute((const void*)gemm_pipe<128, 128, 4, 2, 1>,
                         cudaFuncAttributeMaxDynamicSharedMemorySize, smem_g128);
    cudaFuncSetAttribute((const void*)gemm_pipe<128, 128, 4, 2, 0>,
                         cudaFuncAttributeMaxDynamicSharedMemorySize, smem_g128);
    cudaFuncSetAttribute((const void*)gemm_pipe<64, 128, 2, 4, 2>,
                         cudaFuncAttributeMaxDynamicSharedMemorySize, smem_g64);
    cudaFuncSetAttribute(flash_wmma,
                         cudaFuncAttributeMaxDynamicSharedMemorySize, FSM);

    // Q projection (scatter into [B,h,L,64])
    gemm_pipe<128, 128, 4, 2, 1><<<dim3(16, 16), 256, smem_g128>>>(
        hs, Wq, nullptr, Qb, nullptr, 2048, 2048, 2048);
    // Fused K+V projection
    gemm_pipe<64, 128, 2, 4, 2><<<dim3(4, 32), 256, smem_g64>>>(
        hs, Wk, Wv, Kb, Vb, 2048, 512, 2048);

    // Cache gather + RoPE
    rope_gather_kernel<<<8192, 256>>>(pk, pv, cosp, sinp);

    // Causal flash attention -> g_AO [B, L, 2048]
    flash_wmma<<<dim3(16, 32, 2), 256, FSM>>>(Qb, Kb, Vb, AO);

    // Output projection
    gemm_pipe<128, 128, 4, 2, 0><<<dim3(16, 16), 256, smem_g128>>>(
        AO, Wo, nullptr, out, nullptr, 2048, 2048, 2048);
}